// round 3
// baseline (speedup 1.0000x reference)
#include <cuda_runtime.h>
#include <math.h>
#include <stdint.h>
#include <float.h>

// ---------------- Scratch (device globals; no allocation allowed) ----------------
__device__ float g_ps[25600 * 196];     // ps_map [160*160][196]
__device__ float g_bb[25600 * 196];     // bb_map [160*160][196]
__device__ float g_off[300 * 4];        // offsets from part2_2(rois)
__device__ float g_roisall[600 * 5];    // rois_all
__device__ float g_scores[600];         // cls_score per roi

// ================= tf32 helpers =================
__device__ __forceinline__ uint32_t f2tf32(float x) {
    uint32_t r;
    asm("cvt.rna.tf32.f32 %0, %1;" : "=r"(r) : "f"(x));
    return r;
}
__device__ __forceinline__ void split1(float x, uint32_t& h, uint32_t& l) {
    h = f2tf32(x);
    float rem = x - __uint_as_float(h);
    l = f2tf32(rem);
}

__device__ __forceinline__ void mma_16n8k8(float c[4], const uint32_t a[4],
                                           uint32_t b0, uint32_t b1) {
    asm volatile(
        "mma.sync.aligned.m16n8k8.row.col.f32.tf32.tf32.f32 "
        "{%0,%1,%2,%3}, {%4,%5,%6,%7}, {%8,%9}, {%0,%1,%2,%3};"
        : "+f"(c[0]), "+f"(c[1]), "+f"(c[2]), "+f"(c[3])
        : "r"(a[0]), "r"(a[1]), "r"(a[2]), "r"(a[3]), "r"(b0), "r"(b1));
}

// ================= tf32x3 GEMM via mma.sync =================
// C[25600 x 392] = feat[25600 x 1024] @ [W_ps | W_bb] + bias
// Grid (200, 7), block 256 (8 warps). BM=128, BN=56, BK=32.
// Warp w computes rows [w*16, w*16+16) x all 56 cols (7 m16n8 tiles).
#define BKk 32
#define ASTR 132            // float stride per k-row (padded, conflict-free frags)
#define BSTR 58             // uint2 stride per k-row
#define OFF_A(buf, split) (((buf) * 2 + (split)) * BKk * ASTR * 4)
#define OFF_B(buf)        (67584 + (buf) * BKk * BSTR * 8)
#define GEMM_SMEM 97280

__global__ __launch_bounds__(256, 1) void gemm_mma(
    const float* __restrict__ A,      // [25600][1024]
    const float* __restrict__ Wps,    // [1024][196]
    const float* __restrict__ bps,    // [196]
    const float* __restrict__ Wbb,    // [1024][196]
    const float* __restrict__ bbb,    // [196]
    float* __restrict__ Cps,          // [25600][196]
    float* __restrict__ Cbb)          // [25600][196]
{
    extern __shared__ char smem[];
    const int tid = threadIdx.x;
    const int lane = tid & 31;
    const int wid = tid >> 5;          // 0..7
    const int mw = wid * 16;
    const int g = lane >> 2;           // 0..7
    const int t = lane & 3;            // 0..3
    const int rowBase = blockIdx.x * 128;
    const int colBase = blockIdx.y * 56;

    float c[7][4];
#pragma unroll
    for (int nt = 0; nt < 7; nt++)
#pragma unroll
        for (int j = 0; j < 4; j++) c[nt][j] = 0.0f;

    float4 aReg[4];
    float bReg[7];

    // ---- stage-load helpers (inlined) ----
    // LDG stage st into regs
    auto ldg = [&](int st) {
#pragma unroll
        for (int i = 0; i < 4; i++) {
            int idx = i * 256 + tid;
            int r = idx >> 3, q = idx & 7;
            aReg[i] = *reinterpret_cast<const float4*>(
                A + (size_t)(rowBase + r) * 1024 + st * 32 + q * 4);
        }
#pragma unroll
        for (int i = 0; i < 7; i++) {
            int idx = i * 256 + tid;
            int k = idx / 56, n = idx - 56 * k;
            int gc = colBase + n;
            bReg[i] = (gc < 196) ? Wps[(size_t)(st * 32 + k) * 196 + gc]
                                 : Wbb[(size_t)(st * 32 + k) * 196 + (gc - 196)];
        }
    };
    // split regs -> smem buffer buf
    auto sts = [&](int buf) {
        uint32_t* AH = reinterpret_cast<uint32_t*>(smem + OFF_A(buf, 0));
        uint32_t* AL = reinterpret_cast<uint32_t*>(smem + OFF_A(buf, 1));
        uint2* BB = reinterpret_cast<uint2*>(smem + OFF_B(buf));
#pragma unroll
        for (int i = 0; i < 4; i++) {
            int idx = i * 256 + tid;
            int r = idx >> 3, q = idx & 7;
            float vv[4] = {aReg[i].x, aReg[i].y, aReg[i].z, aReg[i].w};
#pragma unroll
            for (int j = 0; j < 4; j++) {
                uint32_t h, l;
                split1(vv[j], h, l);
                AH[(q * 4 + j) * ASTR + r] = h;
                AL[(q * 4 + j) * ASTR + r] = l;
            }
        }
#pragma unroll
        for (int i = 0; i < 7; i++) {
            int idx = i * 256 + tid;
            int k = idx / 56, n = idx - 56 * k;
            uint32_t h, l;
            split1(bReg[i], h, l);
            BB[k * BSTR + n] = make_uint2(h, l);
        }
    };

    // prologue
    ldg(0);
    sts(0);
    __syncthreads();

    for (int st = 0; st < 32; ++st) {
        const int buf = st & 1;
        if (st < 31) ldg(st + 1);

        const uint32_t* AH = reinterpret_cast<const uint32_t*>(smem + OFF_A(buf, 0));
        const uint32_t* AL = reinterpret_cast<const uint32_t*>(smem + OFF_A(buf, 1));
        const uint2* BB = reinterpret_cast<const uint2*>(smem + OFF_B(buf));

#pragma unroll
        for (int kk = 0; kk < 4; kk++) {
            const int k0 = kk * 8;
            uint32_t ah[4], al[4];
            ah[0] = AH[(k0 + t) * ASTR + mw + g];
            ah[1] = AH[(k0 + t) * ASTR + mw + g + 8];
            ah[2] = AH[(k0 + t + 4) * ASTR + mw + g];
            ah[3] = AH[(k0 + t + 4) * ASTR + mw + g + 8];
            al[0] = AL[(k0 + t) * ASTR + mw + g];
            al[1] = AL[(k0 + t) * ASTR + mw + g + 8];
            al[2] = AL[(k0 + t + 4) * ASTR + mw + g];
            al[3] = AL[(k0 + t + 4) * ASTR + mw + g + 8];
#pragma unroll
            for (int nt = 0; nt < 7; nt++) {
                uint2 v0 = BB[(k0 + t) * BSTR + nt * 8 + g];
                uint2 v1 = BB[(k0 + t + 4) * BSTR + nt * 8 + g];
                // lo_a*hi_b + hi_a*lo_b + hi_a*hi_b
                mma_16n8k8(c[nt], al, v0.x, v1.x);
                mma_16n8k8(c[nt], ah, v0.y, v1.y);
                mma_16n8k8(c[nt], ah, v0.x, v1.x);
            }
        }
        if (st < 31) sts(buf ^ 1);
        __syncthreads();
    }

    // ---- epilogue: bias + float2 stores ----
#pragma unroll
    for (int nt = 0; nt < 7; nt++) {
        int gc = colBase + nt * 8 + t * 2;      // even; pair never straddles 196
        float bias0, bias1;
        float* Cout;
        int cc;
        if (gc < 196) { bias0 = bps[gc]; bias1 = bps[gc + 1]; Cout = Cps; cc = gc; }
        else { bias0 = bbb[gc - 196]; bias1 = bbb[gc - 195]; Cout = Cbb; cc = gc - 196; }
        int r0 = rowBase + mw + g;
        float2 w0 = make_float2(c[nt][0] + bias0, c[nt][1] + bias1);
        float2 w1 = make_float2(c[nt][2] + bias0, c[nt][3] + bias1);
        *reinterpret_cast<float2*>(&Cout[(size_t)r0 * 196 + cc]) = w0;
        *reinterpret_cast<float2*>(&Cout[(size_t)(r0 + 8) * 196 + cc]) = w1;
    }
}

// ---------------- Bilinear PS-ROI sample: 4 channels p*49 + i*7 + j --------------
__device__ __forceinline__ void ps_sample4(const float* __restrict__ map,
                                           float y, float x, int cbase, float v[4])
{
    float y0f = floorf(y), x0f = floorf(x);
    float wy = y - y0f, wx = x - x0f;
    int y0 = (int)y0f; y0 = min(max(y0, 0), 159);
    int y1c = min(y0 + 1, 159);
    int x0 = (int)x0f; x0 = min(max(x0, 0), 159);
    int x1c = min(x0 + 1, 159);

    const float* p00 = map + (size_t)(y0 * 160 + x0) * 196 + cbase;
    const float* p01 = map + (size_t)(y0 * 160 + x1c) * 196 + cbase;
    const float* p10 = map + (size_t)(y1c * 160 + x0) * 196 + cbase;
    const float* p11 = map + (size_t)(y1c * 160 + x1c) * 196 + cbase;

    float w00 = (1.0f - wy) * (1.0f - wx);
    float w01 = (1.0f - wy) * wx;
    float w10 = wy * (1.0f - wx);
    float w11 = wy * wx;
#pragma unroll
    for (int p = 0; p < 4; p++) {
        v[p] = p00[p * 49] * w00 + p01[p * 49] * w01 +
               p10[p * 49] * w10 + p11[p * 49] * w11;
    }
}

// ---------------- part2_2: pooled 4-vector per roi -------------------------------
__global__ __launch_bounds__(256) void pooled4_kernel(
    const float* __restrict__ rois,   // [n][5]
    const float* __restrict__ map,    // [25600][196]
    float* __restrict__ out)          // [n][4]
{
    int r = blockIdx.x;
    const float* roi = rois + (size_t)r * 5;
    float x1 = roi[1] * 0.125f;
    float yy1 = roi[2] * 0.125f;
    float x2 = roi[3] * 0.125f;
    float y2 = roi[4] * 0.125f;
    float bw = __fdiv_rn(x2 - x1, 7.0f);
    float bh = __fdiv_rn(y2 - yy1, 7.0f);

    int t = threadIdx.x;
    float v[4] = {0.f, 0.f, 0.f, 0.f};
    if (t < 196) {
        int yI = t / 14, xI = t % 14;
        int i = yI >> 1, sy = yI & 1;
        int j = xI >> 1, sx = xI & 1;
        float y = __fmaf_rn((float)i + (sy ? 0.75f : 0.25f), bh, yy1);
        float x = __fmaf_rn((float)j + (sx ? 0.75f : 0.25f), bw, x1);
        ps_sample4(map, y, x, i * 7 + j, v);
    }

    __shared__ float red[4][256];
#pragma unroll
    for (int p = 0; p < 4; p++) red[p][t] = v[p];
    __syncthreads();
    for (int s = 128; s > 0; s >>= 1) {
        if (t < s) {
#pragma unroll
            for (int p = 0; p < 4; p++) red[p][t] += red[p][t + s];
        }
        __syncthreads();
    }
    if (t < 4) out[(size_t)r * 4 + t] = __fdiv_rn(red[t][0], 196.0f);
}

// ---------------- proposals: bbox_transform_inv + clip + assemble rois_all -------
__global__ void proposal_kernel(const float* __restrict__ rois,   // [300][5]
                                const float* __restrict__ off,    // [300][4]
                                float* __restrict__ roisall,      // [600][5]
                                float* __restrict__ out_roisall)  // d_out section
{
    int r = blockIdx.x * blockDim.x + threadIdx.x;
    if (r >= 300) return;

#pragma unroll
    for (int c = 0; c < 5; c++) {
        float val = rois[(size_t)r * 5 + c];
        roisall[(size_t)r * 5 + c] = val;
        out_roisall[(size_t)r * 5 + c] = val;
    }

    float x1 = rois[r * 5 + 1], y1 = rois[r * 5 + 2];
    float x2 = rois[r * 5 + 3], y2 = rois[r * 5 + 4];
    float w = x2 - x1 + 1.0f, h = y2 - y1 + 1.0f;
    float cx = x1 + 0.5f * w, cy = y1 + 0.5f * h;
    float dx = off[r * 4 + 0], dy = off[r * 4 + 1];
    float dw = off[r * 4 + 2], dh = off[r * 4 + 3];
    float pcx = dx * w + cx, pcy = dy * h + cy;
    float edw = (float)exp((double)dw);
    float edh = (float)exp((double)dh);
    float pw = edw * w, ph = edh * h;
    float px1 = pcx - 0.5f * pw, py1 = pcy - 0.5f * ph;
    float px2 = pcx + 0.5f * pw, py2 = pcy + 0.5f * ph;
    px1 = fminf(fmaxf(px1, 0.0f), 1279.0f);
    py1 = fminf(fmaxf(py1, 0.0f), 1279.0f);
    px2 = fminf(fmaxf(px2, 0.0f), 1279.0f);
    py2 = fminf(fmaxf(py2, 0.0f), 1279.0f);

    int rr = 300 + r;
    float vals[5] = {0.0f, px1, py1, px2, py2};
#pragma unroll
    for (int c = 0; c < 5; c++) {
        roisall[(size_t)rr * 5 + c] = vals[c];
        out_roisall[(size_t)rr * 5 + c] = vals[c];
    }
}

// ---------------- part2_1: cls / cls_result / cls_score / mask_result ------------
__global__ __launch_bounds__(256) void cls_mask_kernel(
    const float* __restrict__ roisall,  // [600][5]
    const float* __restrict__ psmap,    // [25600][196]
    float* __restrict__ out_cls,        // [600][2]
    float* __restrict__ out_res,        // [600]
    float* __restrict__ out_score,      // [600]
    float* __restrict__ out_mask,       // [600][14][14][2]
    float* __restrict__ scores)         // [600]
{
    int r = blockIdx.x;
    const float* roi = roisall + (size_t)r * 5;
    float x1 = roi[1] * 0.125f;
    float yy1 = roi[2] * 0.125f;
    float x2 = roi[3] * 0.125f;
    float y2 = roi[4] * 0.125f;
    float bw = __fdiv_rn(x2 - x1, 7.0f);
    float bh = __fdiv_rn(y2 - yy1, 7.0f);

    int t = threadIdx.x;
    float v[4] = {0.f, 0.f, 0.f, 0.f};
    float cm0 = 0.f, cm1 = 0.f;
    if (t < 196) {
        int yI = t / 14, xI = t % 14;
        int i = yI >> 1, sy = yI & 1;
        int j = xI >> 1, sx = xI & 1;
        float y = __fmaf_rn((float)i + (sy ? 0.75f : 0.25f), bh, yy1);
        float x = __fmaf_rn((float)j + (sx ? 0.75f : 0.25f), bw, x1);
        ps_sample4(psmap, y, x, i * 7 + j, v);
        cm0 = fmaxf(v[0], v[2]);
        cm1 = fmaxf(v[1], v[3]);
    }

    __shared__ float red[2][256];
    __shared__ int s_res;
    red[0][t] = cm0;
    red[1][t] = cm1;
    __syncthreads();
    for (int s = 128; s > 0; s >>= 1) {
        if (t < s) {
            red[0][t] += red[0][t + s];
            red[1][t] += red[1][t + s];
        }
        __syncthreads();
    }
    if (t == 0) {
        float a0 = __fdiv_rn(red[0][0], 196.0f);
        float a1 = __fdiv_rn(red[1][0], 196.0f);
        double m = (a0 > a1) ? (double)a0 : (double)a1;
        double e0 = exp((double)a0 - m);
        double e1 = exp((double)a1 - m);
        double inv = 1.0 / (e0 + e1);
        float c0 = (float)(e0 * inv);
        float c1 = (float)(e1 * inv);
        int res = (c1 > c0) ? 1 : 0;
        float sc = fmaxf(c0, c1);
        out_cls[(size_t)r * 2 + 0] = c0;
        out_cls[(size_t)r * 2 + 1] = c1;
        out_res[r] = (float)res;
        out_score[r] = sc;
        scores[r] = sc;
        s_res = res;
    }
    __syncthreads();

    if (t < 196) {
        int copy = s_res;
        float m0 = v[copy], m1 = v[2 + copy];
        float mm = fmaxf(m0, m1);
        float e0 = expf(m0 - mm);
        float e1 = expf(m1 - mm);
        float s = e0 + e1;
        out_mask[(size_t)r * 392 + t * 2 + 0] = __fdiv_rn(e0, s);
        out_mask[(size_t)r * 392 + t * 2 + 1] = __fdiv_rn(e1, s);
    }
}

// ---------------- NMS (single block, 640 threads) --------------------------------
__global__ __launch_bounds__(640) void nms_kernel(
    const float* __restrict__ roisall,   // [600][5]
    const float* __restrict__ scores,    // [600]
    float* __restrict__ out_keep)        // [300]
{
    __shared__ float s_sc[600];
    __shared__ int s_ord[600];
    __shared__ float bxs[600 * 4];
    __shared__ float s_area[600];
    __shared__ unsigned char s_kept[600];

    int t = threadIdx.x;
    if (t < 600) s_sc[t] = scores[t];
    __syncthreads();

    if (t < 600) {
        float si = s_sc[t];
        int cnt = 0;
        for (int j = 0; j < 600; j++) {
            float sj = s_sc[j];
            cnt += (sj > si) || (sj == si && j < t);
        }
        s_ord[cnt] = t;
    }
    __syncthreads();

    float bx1 = 0.f, by1 = 0.f, bx2 = 0.f, by2 = 0.f, myArea = 0.f;
    bool kept_self = false;
    if (t < 600) {
        int o = s_ord[t];
        bx1 = roisall[(size_t)o * 5 + 1];
        by1 = roisall[(size_t)o * 5 + 2];
        bx2 = roisall[(size_t)o * 5 + 3];
        by2 = roisall[(size_t)o * 5 + 4];
        myArea = fmaxf(bx2 - bx1, 0.0f) * fmaxf(by2 - by1, 0.0f);
        bxs[t * 4 + 0] = bx1;
        bxs[t * 4 + 1] = by1;
        bxs[t * 4 + 2] = bx2;
        bxs[t * 4 + 3] = by2;
        s_area[t] = myArea;
    }
    __syncthreads();

    for (int i = 0; i < 600; i++) {
        bool p = false;
        if (t < i && kept_self) {
            float cx1 = bxs[i * 4 + 0], cy1 = bxs[i * 4 + 1];
            float cx2 = bxs[i * 4 + 2], cy2 = bxs[i * 4 + 3];
            float ix1 = fmaxf(cx1, bx1), iy1 = fmaxf(cy1, by1);
            float ix2 = fminf(cx2, bx2), iy2 = fminf(cy2, by2);
            float inter = fmaxf(ix2 - ix1, 0.0f) * fmaxf(iy2 - iy1, 0.0f);
            float denom = s_area[i] + myArea - inter + 1e-8f;
            float iou = __fdiv_rn(inter, denom);
            p = iou > 0.3f;
        }
        int any = __syncthreads_or((int)p);
        if (t == i) kept_self = !any;
    }

    if (t < 600) s_kept[t] = kept_self ? 1 : 0;
    __syncthreads();

    if (t == 0) {
        int rc = 0;
        for (int p2 = 0; p2 < 600 && rc < 300; p2++) {
            if (s_kept[p2]) out_keep[rc++] = (float)s_ord[p2];
        }
        for (; rc < 300; rc++) out_keep[rc] = -1.0f;
    }
}

// ---------------- launch ----------------------------------------------------------
extern "C" void kernel_launch(void* const* d_in, const int* in_sizes, int n_in,
                              void* d_out, int out_size)
{
    const float* feat = (const float*)d_in[0];   // [1,160,160,1024]
    const float* Wps  = (const float*)d_in[1];   // [1024,196]
    const float* bps  = (const float*)d_in[2];   // [196]
    const float* Wbb  = (const float*)d_in[3];   // [1024,196]
    const float* bbb  = (const float*)d_in[4];   // [196]
    const float* rois = (const float*)d_in[5];   // [300,5]

    float* out = (float*)d_out;
    float* o_cls  = out;            // 600*2   = 1200
    float* o_res  = out + 1200;     // 600
    float* o_sc   = out + 1800;     // 600
    float* o_mask = out + 2400;     // 600*14*14*2 = 235200
    float* o_ra   = out + 237600;   // 600*5 = 3000
    float* o_bb   = out + 240600;   // 600*4 = 2400
    float* o_keep = out + 243000;   // 300

    float *p_ps, *p_bb, *p_off, *p_ra, *p_sc;
    cudaGetSymbolAddress((void**)&p_ps, g_ps);
    cudaGetSymbolAddress((void**)&p_bb, g_bb);
    cudaGetSymbolAddress((void**)&p_off, g_off);
    cudaGetSymbolAddress((void**)&p_ra, g_roisall);
    cudaGetSymbolAddress((void**)&p_sc, g_scores);

    cudaFuncSetAttribute(gemm_mma, cudaFuncAttributeMaxDynamicSharedMemorySize,
                         GEMM_SMEM);

    // 1. feature maps (mma.sync tf32x3)
    gemm_mma<<<dim3(200, 7), 256, GEMM_SMEM>>>(feat, Wps, bps, Wbb, bbb, p_ps, p_bb);
    // 2. offsets for the original 300 rois
    pooled4_kernel<<<300, 256>>>(rois, p_bb, p_off);
    // 3. proposals + rois_all
    proposal_kernel<<<2, 256>>>(rois, p_off, p_ra, o_ra);
    // 4. bbox for all 600 rois
    pooled4_kernel<<<600, 256>>>(p_ra, p_bb, o_bb);
    // 5. cls / score / mask for all 600 rois
    cls_mask_kernel<<<600, 256>>>(p_ra, p_ps, o_cls, o_res, o_sc, o_mask, p_sc);
    // 6. NMS
    nms_kernel<<<1, 640>>>(p_ra, p_sc, o_keep);
}

// round 4
// speedup vs baseline: 1.6056x; 1.6056x over previous
#include <cuda_runtime.h>
#include <math.h>
#include <stdint.h>
#include <float.h>

// ---------------- Scratch (device globals; no allocation allowed) ----------------
__device__ float g_ps[25600 * 196];     // ps_map
__device__ float g_bb[25600 * 196];     // bb_map
__device__ float g_off[300 * 4];
__device__ float g_roisall[600 * 5];
__device__ float g_scores[600];
// pre-split operands (frag-ordered)
__device__ float4 g_Ah4[6553600];       // 100 MB
__device__ float4 g_Al4[6553600];       // 100 MB
__device__ uint4  g_Bsp[200704];        // 3.2 MB  [cb][kt][kk][nt][lane]

// ================= helpers =================
__device__ __forceinline__ uint32_t f2tf32(float x) {
    uint32_t r;
    asm("cvt.rna.tf32.f32 %0, %1;" : "=r"(r) : "f"(x));
    return r;
}
__device__ __forceinline__ void split1(float x, uint32_t& h, uint32_t& l) {
    h = f2tf32(x);
    float rem = x - __uint_as_float(h);
    l = f2tf32(rem);
}
__device__ __forceinline__ uint32_t smem_u32(const void* p) {
    uint32_t a;
    asm("{ .reg .u64 t; cvta.to.shared.u64 t, %1; cvt.u32.u64 %0, t; }" : "=r"(a) : "l"(p));
    return a;
}
__device__ __forceinline__ void cpa16(uint32_t saddr, const void* gptr) {
    asm volatile("cp.async.cg.shared.global [%0], [%1], 16;" :: "r"(saddr), "l"(gptr));
}
#define CP_COMMIT() asm volatile("cp.async.commit_group;" ::: "memory")
#define CP_WAIT1()  asm volatile("cp.async.wait_group 1;" ::: "memory")
#define CP_WAIT0()  asm volatile("cp.async.wait_group 0;" ::: "memory")

__device__ __forceinline__ void mma_16n8k8(float c[4], const uint32_t a[4],
                                           uint32_t b0, uint32_t b1) {
    asm volatile(
        "mma.sync.aligned.m16n8k8.row.col.f32.tf32.tf32.f32 "
        "{%0,%1,%2,%3}, {%4,%5,%6,%7}, {%8,%9}, {%0,%1,%2,%3};"
        : "+f"(c[0]), "+f"(c[1]), "+f"(c[2]), "+f"(c[3])
        : "r"(a[0]), "r"(a[1]), "r"(a[2]), "r"(a[3]), "r"(b0), "r"(b1));
}

// ================= prep: split feat into frag-ordered hi/lo planes ================
// Output float4 index i -> (rt, kt, rg, kk, lane); regs = {(g,t),(g+8,t),(g,t+4),(g+8,t+4)}
__global__ __launch_bounds__(256) void prep_A(const float* __restrict__ feat,
                                              float4* __restrict__ Ah4,
                                              float4* __restrict__ Al4)
{
    long i = (long)blockIdx.x * 256 + threadIdx.x;   // 0 .. 6,553,599
    int lane = (int)(i & 31);
    int kk = (int)((i >> 5) & 3);
    int rg = (int)((i >> 7) & 7);
    long blk = i >> 10;
    int kt = (int)(blk & 31);
    long rt = blk >> 5;
    int g = lane >> 2, t = lane & 3;
    long r = rt * 128 + rg * 16 + g;
    int k = kt * 32 + kk * 8 + t;
    const float* p = feat + r * 1024 + k;
    float f0 = p[0];
    float f1 = p[8 * 1024];
    float f2 = p[4];
    float f3 = p[8 * 1024 + 4];
    uint32_t h0, l0, h1, l1, h2, l2, h3, l3;
    split1(f0, h0, l0); split1(f1, h1, l1);
    split1(f2, h2, l2); split1(f3, h3, l3);
    Ah4[i] = make_float4(__uint_as_float(h0), __uint_as_float(h1),
                         __uint_as_float(h2), __uint_as_float(h3));
    Al4[i] = make_float4(__uint_as_float(l0), __uint_as_float(l1),
                         __uint_as_float(l2), __uint_as_float(l3));
}

// ================= prep: split W into frag-ordered B ================
// uint4 = (bh@k=t, bh@k=t+4, bl@k=t, bl@k=t+4); n = NBASE + nt*8 + g
__global__ __launch_bounds__(256) void prep_B(const float* __restrict__ Wps,
                                              const float* __restrict__ Wbb,
                                              uint4* __restrict__ Bsp)
{
    int i = blockIdx.x * 256 + threadIdx.x;          // 0 .. 200,703
    if (i >= 200704) return;
    int cb, ntc, nbase, base;
    if (i < 102400) { cb = 0; ntc = 25; nbase = 0; base = 0; }
    else            { cb = 1; ntc = 24; nbase = 200; base = 102400; }
    int li = i - base;
    int lane = li & 31;
    int j = li >> 5;
    int nt = j % ntc; j /= ntc;
    int kk = j & 3;
    int kt = j >> 2;
    int g = lane >> 2, t = lane & 3;
    int n = nbase + nt * 8 + g;
    int k0 = kt * 32 + kk * 8 + t;
    float w0 = (n < 196) ? Wps[(size_t)k0 * 196 + n] : Wbb[(size_t)k0 * 196 + (n - 196)];
    float w1 = (n < 196) ? Wps[(size_t)(k0 + 4) * 196 + n] : Wbb[(size_t)(k0 + 4) * 196 + (n - 196)];
    uint32_t h0, l0, h1, l1;
    split1(w0, h0, l0);
    split1(w1, h1, l1);
    Bsp[i] = make_uint4(h0, h1, l0, l1);
    (void)cb;
}

// ================= GEMM: tf32x3 via mma.sync, frag-ordered operands ================
// grid (200, 2). CTA = 128 rows x NTC*8 cols, 8 warps (16 rows each), BK=32, 32 stages.
template<int NTC, int NBASE, int BOFF>
__device__ __forceinline__ void gemm_body(
    const float4* __restrict__ Ah4, const float4* __restrict__ Al4,
    const uint4* __restrict__ Bsp,
    const float* __restrict__ bps, const float* __restrict__ bbb,
    float* __restrict__ Cps, float* __restrict__ Cbb, char* smem)
{
    constexpr int BSTAGE = NTC * 4 * 32;     // uint4 per stage
    const int tid = threadIdx.x;
    const int lane = tid & 31;
    const int wid = tid >> 5;
    const int g = lane >> 2;
    const int t = lane & 3;
    const long rt = blockIdx.x;

    // smem: A hi/lo 2 bufs [0,64K), B 2 bufs at 64K
    const uint32_t sbase = smem_u32(smem);
    float c[NTC][4];
#pragma unroll
    for (int nt = 0; nt < NTC; nt++)
#pragma unroll
        for (int j = 0; j < 4; j++) c[nt][j] = 0.0f;

    auto copy_stage = [&](int s) {
        int buf = s & 1;
        const float4* gh = Ah4 + (rt * 32 + s) * 1024;
        const float4* gl = Al4 + (rt * 32 + s) * 1024;
        uint32_t sah = sbase + buf * 32768;
        uint32_t sal = sah + 16384;
#pragma unroll
        for (int i = 0; i < 4; i++) {
            int o = tid + i * 256;
            cpa16(sah + o * 16, gh + o);
            cpa16(sal + o * 16, gl + o);
        }
        const uint4* gb = Bsp + BOFF + s * BSTAGE;
        uint32_t sB = sbase + 65536 + buf * (BSTAGE * 16);
        for (int o = tid; o < BSTAGE; o += 256)
            cpa16(sB + o * 16, gb + o);
        CP_COMMIT();
    };

    copy_stage(0);
    copy_stage(1);

    for (int s = 0; s < 32; ++s) {
        if (s < 31) CP_WAIT1(); else CP_WAIT0();
        __syncthreads();

        const int buf = s & 1;
        const float4* Ah = reinterpret_cast<const float4*>(smem + buf * 32768);
        const float4* Al = reinterpret_cast<const float4*>(smem + buf * 32768 + 16384);
        const uint4* Bs = reinterpret_cast<const uint4*>(smem + 65536 + buf * (BSTAGE * 16));

#pragma unroll
        for (int kk = 0; kk < 4; kk++) {
            float4 hv = Ah[(wid * 4 + kk) * 32 + lane];
            float4 lv = Al[(wid * 4 + kk) * 32 + lane];
            uint32_t ah[4] = {__float_as_uint(hv.x), __float_as_uint(hv.y),
                              __float_as_uint(hv.z), __float_as_uint(hv.w)};
            uint32_t al[4] = {__float_as_uint(lv.x), __float_as_uint(lv.y),
                              __float_as_uint(lv.z), __float_as_uint(lv.w)};
#pragma unroll
            for (int nt = 0; nt < NTC; nt++) {
                uint4 q = Bs[(kk * NTC + nt) * 32 + lane];
                mma_16n8k8(c[nt], al, q.x, q.y);   // lo_a * hi_b
                mma_16n8k8(c[nt], ah, q.z, q.w);   // hi_a * lo_b
                mma_16n8k8(c[nt], ah, q.x, q.y);   // hi_a * hi_b
            }
        }
        __syncthreads();
        if (s + 2 < 32) copy_stage(s + 2);
    }

    // epilogue: bias + float2 stores (pairs never straddle the 196 boundary)
    const int r0 = (int)rt * 128 + wid * 16 + g;
#pragma unroll
    for (int nt = 0; nt < NTC; nt++) {
        int gc = NBASE + nt * 8 + t * 2;
        float bias0, bias1;
        float* Cout;
        int cc;
        if (gc < 196) { bias0 = bps[gc]; bias1 = bps[gc + 1]; Cout = Cps; cc = gc; }
        else { bias0 = bbb[gc - 196]; bias1 = bbb[gc - 195]; Cout = Cbb; cc = gc - 196; }
        float2 w0 = make_float2(c[nt][0] + bias0, c[nt][1] + bias1);
        float2 w1 = make_float2(c[nt][2] + bias0, c[nt][3] + bias1);
        *reinterpret_cast<float2*>(&Cout[(size_t)r0 * 196 + cc]) = w0;
        *reinterpret_cast<float2*>(&Cout[(size_t)(r0 + 8) * 196 + cc]) = w1;
    }
}

#define GEMM_SMEM (65536 + 2 * 25 * 4 * 32 * 16)   // 167936

__global__ __launch_bounds__(256, 1) void gemm_mma(
    const float4* __restrict__ Ah4, const float4* __restrict__ Al4,
    const uint4* __restrict__ Bsp,
    const float* __restrict__ bps, const float* __restrict__ bbb,
    float* __restrict__ Cps, float* __restrict__ Cbb)
{
    extern __shared__ char smem[];
    if (blockIdx.y == 0)
        gemm_body<25, 0, 0>(Ah4, Al4, Bsp, bps, bbb, Cps, Cbb, smem);
    else
        gemm_body<24, 200, 102400>(Ah4, Al4, Bsp, bps, bbb, Cps, Cbb, smem);
}

// ---------------- Bilinear PS-ROI sample ----------------
__device__ __forceinline__ void ps_sample4(const float* __restrict__ map,
                                           float y, float x, int cbase, float v[4])
{
    float y0f = floorf(y), x0f = floorf(x);
    float wy = y - y0f, wx = x - x0f;
    int y0 = (int)y0f; y0 = min(max(y0, 0), 159);
    int y1c = min(y0 + 1, 159);
    int x0 = (int)x0f; x0 = min(max(x0, 0), 159);
    int x1c = min(x0 + 1, 159);

    const float* p00 = map + (size_t)(y0 * 160 + x0) * 196 + cbase;
    const float* p01 = map + (size_t)(y0 * 160 + x1c) * 196 + cbase;
    const float* p10 = map + (size_t)(y1c * 160 + x0) * 196 + cbase;
    const float* p11 = map + (size_t)(y1c * 160 + x1c) * 196 + cbase;

    float w00 = (1.0f - wy) * (1.0f - wx);
    float w01 = (1.0f - wy) * wx;
    float w10 = wy * (1.0f - wx);
    float w11 = wy * wx;
#pragma unroll
    for (int p = 0; p < 4; p++) {
        v[p] = p00[p * 49] * w00 + p01[p * 49] * w01 +
               p10[p * 49] * w10 + p11[p * 49] * w11;
    }
}

// ---------------- part2_2: pooled 4-vector per roi ----------------
__global__ __launch_bounds__(256) void pooled4_kernel(
    const float* __restrict__ rois,
    const float* __restrict__ map,
    float* __restrict__ out)
{
    int r = blockIdx.x;
    const float* roi = rois + (size_t)r * 5;
    float x1 = roi[1] * 0.125f;
    float yy1 = roi[2] * 0.125f;
    float x2 = roi[3] * 0.125f;
    float y2 = roi[4] * 0.125f;
    float bw = __fdiv_rn(x2 - x1, 7.0f);
    float bh = __fdiv_rn(y2 - yy1, 7.0f);

    int t = threadIdx.x;
    float v[4] = {0.f, 0.f, 0.f, 0.f};
    if (t < 196) {
        int yI = t / 14, xI = t % 14;
        int i = yI >> 1, sy = yI & 1;
        int j = xI >> 1, sx = xI & 1;
        float y = __fmaf_rn((float)i + (sy ? 0.75f : 0.25f), bh, yy1);
        float x = __fmaf_rn((float)j + (sx ? 0.75f : 0.25f), bw, x1);
        ps_sample4(map, y, x, i * 7 + j, v);
    }

    __shared__ float red[4][256];
#pragma unroll
    for (int p = 0; p < 4; p++) red[p][t] = v[p];
    __syncthreads();
    for (int s = 128; s > 0; s >>= 1) {
        if (t < s) {
#pragma unroll
            for (int p = 0; p < 4; p++) red[p][t] += red[p][t + s];
        }
        __syncthreads();
    }
    if (t < 4) out[(size_t)r * 4 + t] = __fdiv_rn(red[t][0], 196.0f);
}

// ---------------- proposals ----------------
__global__ void proposal_kernel(const float* __restrict__ rois,
                                const float* __restrict__ off,
                                float* __restrict__ roisall,
                                float* __restrict__ out_roisall)
{
    int r = blockIdx.x * blockDim.x + threadIdx.x;
    if (r >= 300) return;

#pragma unroll
    for (int c = 0; c < 5; c++) {
        float val = rois[(size_t)r * 5 + c];
        roisall[(size_t)r * 5 + c] = val;
        out_roisall[(size_t)r * 5 + c] = val;
    }

    float x1 = rois[r * 5 + 1], y1 = rois[r * 5 + 2];
    float x2 = rois[r * 5 + 3], y2 = rois[r * 5 + 4];
    float w = x2 - x1 + 1.0f, h = y2 - y1 + 1.0f;
    float cx = x1 + 0.5f * w, cy = y1 + 0.5f * h;
    float dx = off[r * 4 + 0], dy = off[r * 4 + 1];
    float dw = off[r * 4 + 2], dh = off[r * 4 + 3];
    float pcx = dx * w + cx, pcy = dy * h + cy;
    float edw = (float)exp((double)dw);
    float edh = (float)exp((double)dh);
    float pw = edw * w, ph = edh * h;
    float px1 = pcx - 0.5f * pw, py1 = pcy - 0.5f * ph;
    float px2 = pcx + 0.5f * pw, py2 = pcy + 0.5f * ph;
    px1 = fminf(fmaxf(px1, 0.0f), 1279.0f);
    py1 = fminf(fmaxf(py1, 0.0f), 1279.0f);
    px2 = fminf(fmaxf(px2, 0.0f), 1279.0f);
    py2 = fminf(fmaxf(py2, 0.0f), 1279.0f);

    int rr = 300 + r;
    float vals[5] = {0.0f, px1, py1, px2, py2};
#pragma unroll
    for (int c = 0; c < 5; c++) {
        roisall[(size_t)rr * 5 + c] = vals[c];
        out_roisall[(size_t)rr * 5 + c] = vals[c];
    }
}

// ---------------- part2_1 ----------------
__global__ __launch_bounds__(256) void cls_mask_kernel(
    const float* __restrict__ roisall,
    const float* __restrict__ psmap,
    float* __restrict__ out_cls,
    float* __restrict__ out_res,
    float* __restrict__ out_score,
    float* __restrict__ out_mask,
    float* __restrict__ scores)
{
    int r = blockIdx.x;
    const float* roi = roisall + (size_t)r * 5;
    float x1 = roi[1] * 0.125f;
    float yy1 = roi[2] * 0.125f;
    float x2 = roi[3] * 0.125f;
    float y2 = roi[4] * 0.125f;
    float bw = __fdiv_rn(x2 - x1, 7.0f);
    float bh = __fdiv_rn(y2 - yy1, 7.0f);

    int t = threadIdx.x;
    float v[4] = {0.f, 0.f, 0.f, 0.f};
    float cm0 = 0.f, cm1 = 0.f;
    if (t < 196) {
        int yI = t / 14, xI = t % 14;
        int i = yI >> 1, sy = yI & 1;
        int j = xI >> 1, sx = xI & 1;
        float y = __fmaf_rn((float)i + (sy ? 0.75f : 0.25f), bh, yy1);
        float x = __fmaf_rn((float)j + (sx ? 0.75f : 0.25f), bw, x1);
        ps_sample4(psmap, y, x, i * 7 + j, v);
        cm0 = fmaxf(v[0], v[2]);
        cm1 = fmaxf(v[1], v[3]);
    }

    __shared__ float red[2][256];
    __shared__ int s_res;
    red[0][t] = cm0;
    red[1][t] = cm1;
    __syncthreads();
    for (int s = 128; s > 0; s >>= 1) {
        if (t < s) {
            red[0][t] += red[0][t + s];
            red[1][t] += red[1][t + s];
        }
        __syncthreads();
    }
    if (t == 0) {
        float a0 = __fdiv_rn(red[0][0], 196.0f);
        float a1 = __fdiv_rn(red[1][0], 196.0f);
        double m = (a0 > a1) ? (double)a0 : (double)a1;
        double e0 = exp((double)a0 - m);
        double e1 = exp((double)a1 - m);
        double inv = 1.0 / (e0 + e1);
        float c0 = (float)(e0 * inv);
        float c1 = (float)(e1 * inv);
        int res = (c1 > c0) ? 1 : 0;
        float sc = fmaxf(c0, c1);
        out_cls[(size_t)r * 2 + 0] = c0;
        out_cls[(size_t)r * 2 + 1] = c1;
        out_res[r] = (float)res;
        out_score[r] = sc;
        scores[r] = sc;
        s_res = res;
    }
    __syncthreads();

    if (t < 196) {
        int copy = s_res;
        float m0 = v[copy], m1 = v[2 + copy];
        float mm = fmaxf(m0, m1);
        float e0 = expf(m0 - mm);
        float e1 = expf(m1 - mm);
        float s = e0 + e1;
        out_mask[(size_t)r * 392 + t * 2 + 0] = __fdiv_rn(e0, s);
        out_mask[(size_t)r * 392 + t * 2 + 1] = __fdiv_rn(e1, s);
    }
}

// ---------------- NMS ----------------
__global__ __launch_bounds__(640) void nms_kernel(
    const float* __restrict__ roisall,
    const float* __restrict__ scores,
    float* __restrict__ out_keep)
{
    __shared__ float s_sc[600];
    __shared__ int s_ord[600];
    __shared__ float bxs[600 * 4];
    __shared__ float s_area[600];
    __shared__ unsigned char s_kept[600];

    int t = threadIdx.x;
    if (t < 600) s_sc[t] = scores[t];
    __syncthreads();

    if (t < 600) {
        float si = s_sc[t];
        int cnt = 0;
        for (int j = 0; j < 600; j++) {
            float sj = s_sc[j];
            cnt += (sj > si) || (sj == si && j < t);
        }
        s_ord[cnt] = t;
    }
    __syncthreads();

    float bx1 = 0.f, by1 = 0.f, bx2 = 0.f, by2 = 0.f, myArea = 0.f;
    bool kept_self = false;
    if (t < 600) {
        int o = s_ord[t];
        bx1 = roisall[(size_t)o * 5 + 1];
        by1 = roisall[(size_t)o * 5 + 2];
        bx2 = roisall[(size_t)o * 5 + 3];
        by2 = roisall[(size_t)o * 5 + 4];
        myArea = fmaxf(bx2 - bx1, 0.0f) * fmaxf(by2 - by1, 0.0f);
        bxs[t * 4 + 0] = bx1;
        bxs[t * 4 + 1] = by1;
        bxs[t * 4 + 2] = bx2;
        bxs[t * 4 + 3] = by2;
        s_area[t] = myArea;
    }
    __syncthreads();

    for (int i = 0; i < 600; i++) {
        bool p = false;
        if (t < i && kept_self) {
            float cx1 = bxs[i * 4 + 0], cy1 = bxs[i * 4 + 1];
            float cx2 = bxs[i * 4 + 2], cy2 = bxs[i * 4 + 3];
            float ix1 = fmaxf(cx1, bx1), iy1 = fmaxf(cy1, by1);
            float ix2 = fminf(cx2, bx2), iy2 = fminf(cy2, by2);
            float inter = fmaxf(ix2 - ix1, 0.0f) * fmaxf(iy2 - iy1, 0.0f);
            float denom = s_area[i] + myArea - inter + 1e-8f;
            float iou = __fdiv_rn(inter, denom);
            p = iou > 0.3f;
        }
        int any = __syncthreads_or((int)p);
        if (t == i) kept_self = !any;
    }

    if (t < 600) s_kept[t] = kept_self ? 1 : 0;
    __syncthreads();

    if (t == 0) {
        int rc = 0;
        for (int p2 = 0; p2 < 600 && rc < 300; p2++) {
            if (s_kept[p2]) out_keep[rc++] = (float)s_ord[p2];
        }
        for (; rc < 300; rc++) out_keep[rc] = -1.0f;
    }
}

// ---------------- launch ----------------
extern "C" void kernel_launch(void* const* d_in, const int* in_sizes, int n_in,
                              void* d_out, int out_size)
{
    const float* feat = (const float*)d_in[0];
    const float* Wps  = (const float*)d_in[1];
    const float* bps  = (const float*)d_in[2];
    const float* Wbb  = (const float*)d_in[3];
    const float* bbb  = (const float*)d_in[4];
    const float* rois = (const float*)d_in[5];

    float* out = (float*)d_out;
    float* o_cls  = out;
    float* o_res  = out + 1200;
    float* o_sc   = out + 1800;
    float* o_mask = out + 2400;
    float* o_ra   = out + 237600;
    float* o_bb   = out + 240600;
    float* o_keep = out + 243000;

    float *p_ps, *p_bb, *p_off, *p_ra, *p_sc;
    float4 *p_Ah, *p_Al;
    uint4 *p_B;
    cudaGetSymbolAddress((void**)&p_ps, g_ps);
    cudaGetSymbolAddress((void**)&p_bb, g_bb);
    cudaGetSymbolAddress((void**)&p_off, g_off);
    cudaGetSymbolAddress((void**)&p_ra, g_roisall);
    cudaGetSymbolAddress((void**)&p_sc, g_scores);
    cudaGetSymbolAddress((void**)&p_Ah, g_Ah4);
    cudaGetSymbolAddress((void**)&p_Al, g_Al4);
    cudaGetSymbolAddress((void**)&p_B, g_Bsp);

    cudaFuncSetAttribute(gemm_mma, cudaFuncAttributeMaxDynamicSharedMemorySize,
                         GEMM_SMEM);

    // 0. pre-split operands into frag order
    prep_A<<<25600, 256>>>(feat, p_Ah, p_Al);
    prep_B<<<784, 256>>>(Wps, Wbb, p_B);
    // 1. feature maps
    gemm_mma<<<dim3(200, 2), 256, GEMM_SMEM>>>(p_Ah, p_Al, p_B, bps, bbb, p_ps, p_bb);
    // 2. offsets for the original 300 rois
    pooled4_kernel<<<300, 256>>>(rois, p_bb, p_off);
    // 3. proposals + rois_all
    proposal_kernel<<<2, 256>>>(rois, p_off, p_ra, o_ra);
    // 4. bbox for all 600 rois
    pooled4_kernel<<<600, 256>>>(p_ra, p_bb, o_bb);
    // 5. cls / score / mask for all 600 rois
    cls_mask_kernel<<<600, 256>>>(p_ra, p_ps, o_cls, o_res, o_sc, o_mask, p_sc);
    // 6. NMS
    nms_kernel<<<1, 640>>>(p_ra, p_sc, o_keep);
}

// round 5
// speedup vs baseline: 2.0975x; 1.3064x over previous
#include <cuda_runtime.h>
#include <cuda_fp16.h>
#include <math.h>
#include <stdint.h>
#include <float.h>

// ---------------- Scratch (device globals; no allocation allowed) ----------------
__device__ float g_ps[25600 * 196];     // ps_map
__device__ float g_bb[25600 * 196];     // bb_map
__device__ float g_off[300 * 4];
__device__ float g_roisall[600 * 5];
__device__ float g_scores[600];
// pre-split fp16 operands, mma-fragment ordered
__device__ uint4 g_Asp[6553600];        // 104.9 MB: [stage 6400][hi 512 | lo 512]
__device__ uint4 g_Bsp[100352];         // 1.6 MB:   [cb][kt][ks][nt][lane] (b0h,b1h,b0l,b1l)

#define A_SCALE 64.0f
#define B_SCALE 1024.0f
#define INV_SCALE (1.0f / 65536.0f)

// ================= helpers =================
__device__ __forceinline__ uint32_t smem_u32(const void* p) {
    uint32_t a;
    asm("{ .reg .u64 t; cvta.to.shared.u64 t, %1; cvt.u32.u64 %0, t; }" : "=r"(a) : "l"(p));
    return a;
}
__device__ __forceinline__ void cpa16(uint32_t saddr, const void* gptr) {
    asm volatile("cp.async.cg.shared.global [%0], [%1], 16;" :: "r"(saddr), "l"(gptr));
}
#define CP_COMMIT() asm volatile("cp.async.commit_group;" ::: "memory")
#define CP_WAIT1()  asm volatile("cp.async.wait_group 1;" ::: "memory")
#define CP_WAIT0()  asm volatile("cp.async.wait_group 0;" ::: "memory")

// fp16 split of (pre-scaled) fp32: x = h + l, drop sub-2^-22 tail
__device__ __forceinline__ void splith(float x, __half& h, __half& l) {
    h = __float2half_rn(x);
    l = __float2half_rn(x - __half2float(h));
}
__device__ __forceinline__ uint32_t packh2(__half a, __half b) {
    __half2 v = __halves2half2(a, b);
    return *reinterpret_cast<uint32_t*>(&v);
}

__device__ __forceinline__ void mma_f16(float c[4], const uint32_t a[4],
                                        uint32_t b0, uint32_t b1) {
    asm volatile(
        "mma.sync.aligned.m16n8k16.row.col.f32.f16.f16.f32 "
        "{%0,%1,%2,%3}, {%4,%5,%6,%7}, {%8,%9}, {%0,%1,%2,%3};"
        : "+f"(c[0]), "+f"(c[1]), "+f"(c[2]), "+f"(c[3])
        : "r"(a[0]), "r"(a[1]), "r"(a[2]), "r"(a[3]), "r"(b0), "r"(b1));
}

// ================= prep_A: feat -> fp16 hi/lo, frag order ================
// thread i -> frag slot: lane=i&31, wid=(i>>5)&7, ks=(i>>8)&1, stage=i>>9
// row = (stage>>5)*128 + wid*16 + g (+8), k = (stage&31)*32 + ks*16 + 2t (+1,+8,+9)
__global__ __launch_bounds__(256) void prep_A(const float* __restrict__ feat,
                                              uint4* __restrict__ Asp)
{
    long i = (long)blockIdx.x * 256 + threadIdx.x;   // 0 .. 3,276,799
    int lane = (int)(i & 31);
    int wid = (int)((i >> 5) & 7);
    int ks = (int)((i >> 8) & 1);
    long stage = i >> 9;                              // rt*32 + kt
    int kt = (int)(stage & 31);
    long rt = stage >> 5;
    int g = lane >> 2, t = lane & 3;
    long row = rt * 128 + wid * 16 + g;
    int k = kt * 32 + ks * 16 + 2 * t;

    const float* p = feat + row * 1024 + k;
    float2 u0 = *reinterpret_cast<const float2*>(p);          // (g,   k..k+1)
    float2 u1 = *reinterpret_cast<const float2*>(p + 8);      // (g,   k+8..k+9)
    float2 u2 = *reinterpret_cast<const float2*>(p + 8192);   // (g+8, k..k+1)
    float2 u3 = *reinterpret_cast<const float2*>(p + 8200);   // (g+8, k+8..k+9)

    __half h0a, l0a, h0b, l0b, h1a, l1a, h1b, l1b;
    __half h2a, l2a, h2b, l2b, h3a, l3a, h3b, l3b;
    splith(u0.x * A_SCALE, h0a, l0a); splith(u0.y * A_SCALE, h0b, l0b);
    splith(u1.x * A_SCALE, h1a, l1a); splith(u1.y * A_SCALE, h1b, l1b);
    splith(u2.x * A_SCALE, h2a, l2a); splith(u2.y * A_SCALE, h2b, l2b);
    splith(u3.x * A_SCALE, h3a, l3a); splith(u3.y * A_SCALE, h3b, l3b);

    // a0=(g,k|k+1)  a1=(g+8,k|k+1)  a2=(g,k+8|k+9)  a3=(g+8,k+8|k+9)
    uint4 hi = make_uint4(packh2(h0a, h0b), packh2(h2a, h2b),
                          packh2(h1a, h1b), packh2(h3a, h3b));
    uint4 lo = make_uint4(packh2(l0a, l0b), packh2(l2a, l2b),
                          packh2(l1a, l1b), packh2(l3a, l3b));
    int slot = (ks * 8 + wid) * 32 + lane;
    Asp[stage * 1024 + slot] = hi;
    Asp[stage * 1024 + 512 + slot] = lo;
}

// ================= prep_B: W -> fp16 hi/lo frag order ================
// uint4 = (b0h, b1h, b0l, b1l); b0 = k rows (2t,2t+1) col n; b1 = k+8 rows.
__global__ __launch_bounds__(256) void prep_B(const float* __restrict__ Wps,
                                              const float* __restrict__ Wbb,
                                              uint4* __restrict__ Bsp)
{
    int i = blockIdx.x * 256 + threadIdx.x;          // 0 .. 100,351
    if (i >= 100352) return;
    int ntc, nbase, base;
    if (i < 51200) { ntc = 25; nbase = 0; base = 0; }
    else           { ntc = 24; nbase = 200; base = 51200; }
    int li = i - base;
    int lane = li & 31;
    int j = li >> 5;
    int nt = j % ntc; j /= ntc;
    int ks = j & 1;
    int kt = j >> 1;
    int g = lane >> 2, t = lane & 3;
    int n = nbase + nt * 8 + g;
    int k = kt * 32 + ks * 16 + 2 * t;

    const float* W = (n < 196) ? Wps : Wbb;
    int nn = (n < 196) ? n : n - 196;
    float w0 = W[(size_t)k * 196 + nn] * B_SCALE;
    float w1 = W[(size_t)(k + 1) * 196 + nn] * B_SCALE;
    float w2 = W[(size_t)(k + 8) * 196 + nn] * B_SCALE;
    float w3 = W[(size_t)(k + 9) * 196 + nn] * B_SCALE;

    __half h0, l0, h1, l1, h2, l2, h3, l3;
    splith(w0, h0, l0); splith(w1, h1, l1);
    splith(w2, h2, l2); splith(w3, h3, l3);
    Bsp[i] = make_uint4(packh2(h0, h1), packh2(h2, h3),
                        packh2(l0, l1), packh2(l2, l3));
}

// ================= GEMM: fp16x3 via mma.sync m16n8k16 ================
// grid (200, 2). CTA = 128 rows x NTC*8 cols, 8 warps, BK=32 (2 k16 steps), 32 stages.
#define GEMM_SMEM (32768 + 2 * 25600)   // A 2x16K, B 2x25.6K = 83968

template<int NTC, int NBASE, int BOFF>
__device__ __forceinline__ void gemm_body(
    const uint4* __restrict__ Asp, const uint4* __restrict__ Bsp,
    const float* __restrict__ bps, const float* __restrict__ bbb,
    float* __restrict__ Cps, float* __restrict__ Cbb, char* smem)
{
    constexpr int BSTAGE = NTC * 64;     // uint4 per stage
    const int tid = threadIdx.x;
    const int lane = tid & 31;
    const int wid = tid >> 5;
    const int g = lane >> 2;
    const int t = lane & 3;
    const long rt = blockIdx.x;
    const uint32_t sbase = smem_u32(smem);

    float c[NTC][4];
#pragma unroll
    for (int nt = 0; nt < NTC; nt++)
#pragma unroll
        for (int j = 0; j < 4; j++) c[nt][j] = 0.0f;

    auto copy_stage = [&](int s) {
        int buf = s & 1;
        const uint4* ga = Asp + ((size_t)(rt * 32 + s)) * 1024;
        uint32_t sa = sbase + buf * 16384;
#pragma unroll
        for (int i = 0; i < 4; i++) {
            int o = tid + i * 256;
            cpa16(sa + o * 16, ga + o);
        }
        const uint4* gb = Bsp + BOFF + (size_t)s * BSTAGE;
        uint32_t sB = sbase + 32768 + buf * 25600;
        for (int o = tid; o < BSTAGE; o += 256)
            cpa16(sB + o * 16, gb + o);
        CP_COMMIT();
    };

    copy_stage(0);
    copy_stage(1);

    for (int s = 0; s < 32; ++s) {
        if (s < 31) CP_WAIT1(); else CP_WAIT0();
        __syncthreads();

        const int buf = s & 1;
        const uint4* Ah = reinterpret_cast<const uint4*>(smem + buf * 16384);
        const uint4* Bs = reinterpret_cast<const uint4*>(smem + 32768 + buf * 25600);

#pragma unroll
        for (int ks = 0; ks < 2; ks++) {
            int slot = (ks * 8 + wid) * 32 + lane;
            uint4 hv = Ah[slot];
            uint4 lv = Ah[512 + slot];
            uint32_t ah[4] = {hv.x, hv.y, hv.z, hv.w};
            uint32_t al[4] = {lv.x, lv.y, lv.z, lv.w};
#pragma unroll
            for (int nt = 0; nt < NTC; nt++) {
                uint4 q = Bs[(ks * NTC + nt) * 32 + lane];
                mma_f16(c[nt], al, q.x, q.y);   // lo_a * hi_b
                mma_f16(c[nt], ah, q.z, q.w);   // hi_a * lo_b
                mma_f16(c[nt], ah, q.x, q.y);   // hi_a * hi_b
            }
        }
        __syncthreads();
        if (s + 2 < 32) copy_stage(s + 2);
    }

    // epilogue: unscale + bias + float2 stores
    const int r0 = (int)rt * 128 + wid * 16 + g;
#pragma unroll
    for (int nt = 0; nt < NTC; nt++) {
        int gc = NBASE + nt * 8 + t * 2;
        float bias0, bias1;
        float* Cout;
        int cc;
        if (gc < 196) { bias0 = bps[gc]; bias1 = bps[gc + 1]; Cout = Cps; cc = gc; }
        else { bias0 = bbb[gc - 196]; bias1 = bbb[gc - 195]; Cout = Cbb; cc = gc - 196; }
        float2 w0 = make_float2(c[nt][0] * INV_SCALE + bias0,
                                c[nt][1] * INV_SCALE + bias1);
        float2 w1 = make_float2(c[nt][2] * INV_SCALE + bias0,
                                c[nt][3] * INV_SCALE + bias1);
        *reinterpret_cast<float2*>(&Cout[(size_t)r0 * 196 + cc]) = w0;
        *reinterpret_cast<float2*>(&Cout[(size_t)(r0 + 8) * 196 + cc]) = w1;
    }
}

__global__ __launch_bounds__(256, 1) void gemm_mma(
    const uint4* __restrict__ Asp, const uint4* __restrict__ Bsp,
    const float* __restrict__ bps, const float* __restrict__ bbb,
    float* __restrict__ Cps, float* __restrict__ Cbb)
{
    extern __shared__ char smem[];
    if (blockIdx.y == 0)
        gemm_body<25, 0, 0>(Asp, Bsp, bps, bbb, Cps, Cbb, smem);
    else
        gemm_body<24, 200, 51200>(Asp, Bsp, bps, bbb, Cps, Cbb, smem);
}

// ---------------- Bilinear PS-ROI sample ----------------
__device__ __forceinline__ void ps_sample4(const float* __restrict__ map,
                                           float y, float x, int cbase, float v[4])
{
    float y0f = floorf(y), x0f = floorf(x);
    float wy = y - y0f, wx = x - x0f;
    int y0 = (int)y0f; y0 = min(max(y0, 0), 159);
    int y1c = min(y0 + 1, 159);
    int x0 = (int)x0f; x0 = min(max(x0, 0), 159);
    int x1c = min(x0 + 1, 159);

    const float* p00 = map + (size_t)(y0 * 160 + x0) * 196 + cbase;
    const float* p01 = map + (size_t)(y0 * 160 + x1c) * 196 + cbase;
    const float* p10 = map + (size_t)(y1c * 160 + x0) * 196 + cbase;
    const float* p11 = map + (size_t)(y1c * 160 + x1c) * 196 + cbase;

    float w00 = (1.0f - wy) * (1.0f - wx);
    float w01 = (1.0f - wy) * wx;
    float w10 = wy * (1.0f - wx);
    float w11 = wy * wx;
#pragma unroll
    for (int p = 0; p < 4; p++) {
        v[p] = p00[p * 49] * w00 + p01[p * 49] * w01 +
               p10[p * 49] * w10 + p11[p * 49] * w11;
    }
}

// ---------------- part2_2: pooled 4-vector per roi ----------------
__global__ __launch_bounds__(256) void pooled4_kernel(
    const float* __restrict__ rois,
    const float* __restrict__ map,
    float* __restrict__ out)
{
    int r = blockIdx.x;
    const float* roi = rois + (size_t)r * 5;
    float x1 = roi[1] * 0.125f;
    float yy1 = roi[2] * 0.125f;
    float x2 = roi[3] * 0.125f;
    float y2 = roi[4] * 0.125f;
    float bw = __fdiv_rn(x2 - x1, 7.0f);
    float bh = __fdiv_rn(y2 - yy1, 7.0f);

    int t = threadIdx.x;
    float v[4] = {0.f, 0.f, 0.f, 0.f};
    if (t < 196) {
        int yI = t / 14, xI = t % 14;
        int i = yI >> 1, sy = yI & 1;
        int j = xI >> 1, sx = xI & 1;
        float y = __fmaf_rn((float)i + (sy ? 0.75f : 0.25f), bh, yy1);
        float x = __fmaf_rn((float)j + (sx ? 0.75f : 0.25f), bw, x1);
        ps_sample4(map, y, x, i * 7 + j, v);
    }

    __shared__ float red[4][256];
#pragma unroll
    for (int p = 0; p < 4; p++) red[p][t] = v[p];
    __syncthreads();
    for (int s = 128; s > 0; s >>= 1) {
        if (t < s) {
#pragma unroll
            for (int p = 0; p < 4; p++) red[p][t] += red[p][t + s];
        }
        __syncthreads();
    }
    if (t < 4) out[(size_t)r * 4 + t] = __fdiv_rn(red[t][0], 196.0f);
}

// ---------------- proposals ----------------
__global__ void proposal_kernel(const float* __restrict__ rois,
                                const float* __restrict__ off,
                                float* __restrict__ roisall,
                                float* __restrict__ out_roisall)
{
    int r = blockIdx.x * blockDim.x + threadIdx.x;
    if (r >= 300) return;

#pragma unroll
    for (int c = 0; c < 5; c++) {
        float val = rois[(size_t)r * 5 + c];
        roisall[(size_t)r * 5 + c] = val;
        out_roisall[(size_t)r * 5 + c] = val;
    }

    float x1 = rois[r * 5 + 1], y1 = rois[r * 5 + 2];
    float x2 = rois[r * 5 + 3], y2 = rois[r * 5 + 4];
    float w = x2 - x1 + 1.0f, h = y2 - y1 + 1.0f;
    float cx = x1 + 0.5f * w, cy = y1 + 0.5f * h;
    float dx = off[r * 4 + 0], dy = off[r * 4 + 1];
    float dw = off[r * 4 + 2], dh = off[r * 4 + 3];
    float pcx = dx * w + cx, pcy = dy * h + cy;
    float edw = (float)exp((double)dw);
    float edh = (float)exp((double)dh);
    float pw = edw * w, ph = edh * h;
    float px1 = pcx - 0.5f * pw, py1 = pcy - 0.5f * ph;
    float px2 = pcx + 0.5f * pw, py2 = pcy + 0.5f * ph;
    px1 = fminf(fmaxf(px1, 0.0f), 1279.0f);
    py1 = fminf(fmaxf(py1, 0.0f), 1279.0f);
    px2 = fminf(fmaxf(px2, 0.0f), 1279.0f);
    py2 = fminf(fmaxf(py2, 0.0f), 1279.0f);

    int rr = 300 + r;
    float vals[5] = {0.0f, px1, py1, px2, py2};
#pragma unroll
    for (int c = 0; c < 5; c++) {
        roisall[(size_t)rr * 5 + c] = vals[c];
        out_roisall[(size_t)rr * 5 + c] = vals[c];
    }
}

// ---------------- part2_1 ----------------
__global__ __launch_bounds__(256) void cls_mask_kernel(
    const float* __restrict__ roisall,
    const float* __restrict__ psmap,
    float* __restrict__ out_cls,
    float* __restrict__ out_res,
    float* __restrict__ out_score,
    float* __restrict__ out_mask,
    float* __restrict__ scores)
{
    int r = blockIdx.x;
    const float* roi = roisall + (size_t)r * 5;
    float x1 = roi[1] * 0.125f;
    float yy1 = roi[2] * 0.125f;
    float x2 = roi[3] * 0.125f;
    float y2 = roi[4] * 0.125f;
    float bw = __fdiv_rn(x2 - x1, 7.0f);
    float bh = __fdiv_rn(y2 - yy1, 7.0f);

    int t = threadIdx.x;
    float v[4] = {0.f, 0.f, 0.f, 0.f};
    float cm0 = 0.f, cm1 = 0.f;
    if (t < 196) {
        int yI = t / 14, xI = t % 14;
        int i = yI >> 1, sy = yI & 1;
        int j = xI >> 1, sx = xI & 1;
        float y = __fmaf_rn((float)i + (sy ? 0.75f : 0.25f), bh, yy1);
        float x = __fmaf_rn((float)j + (sx ? 0.75f : 0.25f), bw, x1);
        ps_sample4(psmap, y, x, i * 7 + j, v);
        cm0 = fmaxf(v[0], v[2]);
        cm1 = fmaxf(v[1], v[3]);
    }

    __shared__ float red[2][256];
    __shared__ int s_res;
    red[0][t] = cm0;
    red[1][t] = cm1;
    __syncthreads();
    for (int s = 128; s > 0; s >>= 1) {
        if (t < s) {
            red[0][t] += red[0][t + s];
            red[1][t] += red[1][t + s];
        }
        __syncthreads();
    }
    if (t == 0) {
        float a0 = __fdiv_rn(red[0][0], 196.0f);
        float a1 = __fdiv_rn(red[1][0], 196.0f);
        double m = (a0 > a1) ? (double)a0 : (double)a1;
        double e0 = exp((double)a0 - m);
        double e1 = exp((double)a1 - m);
        double inv = 1.0 / (e0 + e1);
        float c0 = (float)(e0 * inv);
        float c1 = (float)(e1 * inv);
        int res = (c1 > c0) ? 1 : 0;
        float sc = fmaxf(c0, c1);
        out_cls[(size_t)r * 2 + 0] = c0;
        out_cls[(size_t)r * 2 + 1] = c1;
        out_res[r] = (float)res;
        out_score[r] = sc;
        scores[r] = sc;
        s_res = res;
    }
    __syncthreads();

    if (t < 196) {
        int copy = s_res;
        float m0 = v[copy], m1 = v[2 + copy];
        float mm = fmaxf(m0, m1);
        float e0 = expf(m0 - mm);
        float e1 = expf(m1 - mm);
        float s = e0 + e1;
        out_mask[(size_t)r * 392 + t * 2 + 0] = __fdiv_rn(e0, s);
        out_mask[(size_t)r * 392 + t * 2 + 1] = __fdiv_rn(e1, s);
    }
}

// ---------------- NMS ----------------
__global__ __launch_bounds__(640) void nms_kernel(
    const float* __restrict__ roisall,
    const float* __restrict__ scores,
    float* __restrict__ out_keep)
{
    __shared__ float s_sc[600];
    __shared__ int s_ord[600];
    __shared__ float bxs[600 * 4];
    __shared__ float s_area[600];
    __shared__ unsigned char s_kept[600];

    int t = threadIdx.x;
    if (t < 600) s_sc[t] = scores[t];
    __syncthreads();

    if (t < 600) {
        float si = s_sc[t];
        int cnt = 0;
        for (int j = 0; j < 600; j++) {
            float sj = s_sc[j];
            cnt += (sj > si) || (sj == si && j < t);
        }
        s_ord[cnt] = t;
    }
    __syncthreads();

    float bx1 = 0.f, by1 = 0.f, bx2 = 0.f, by2 = 0.f, myArea = 0.f;
    bool kept_self = false;
    if (t < 600) {
        int o = s_ord[t];
        bx1 = roisall[(size_t)o * 5 + 1];
        by1 = roisall[(size_t)o * 5 + 2];
        bx2 = roisall[(size_t)o * 5 + 3];
        by2 = roisall[(size_t)o * 5 + 4];
        myArea = fmaxf(bx2 - bx1, 0.0f) * fmaxf(by2 - by1, 0.0f);
        bxs[t * 4 + 0] = bx1;
        bxs[t * 4 + 1] = by1;
        bxs[t * 4 + 2] = bx2;
        bxs[t * 4 + 3] = by2;
        s_area[t] = myArea;
    }
    __syncthreads();

    for (int i = 0; i < 600; i++) {
        bool p = false;
        if (t < i && kept_self) {
            float cx1 = bxs[i * 4 + 0], cy1 = bxs[i * 4 + 1];
            float cx2 = bxs[i * 4 + 2], cy2 = bxs[i * 4 + 3];
            float ix1 = fmaxf(cx1, bx1), iy1 = fmaxf(cy1, by1);
            float ix2 = fminf(cx2, bx2), iy2 = fminf(cy2, by2);
            float inter = fmaxf(ix2 - ix1, 0.0f) * fmaxf(iy2 - iy1, 0.0f);
            float denom = s_area[i] + myArea - inter + 1e-8f;
            float iou = __fdiv_rn(inter, denom);
            p = iou > 0.3f;
        }
        int any = __syncthreads_or((int)p);
        if (t == i) kept_self = !any;
    }

    if (t < 600) s_kept[t] = kept_self ? 1 : 0;
    __syncthreads();

    if (t == 0) {
        int rc = 0;
        for (int p2 = 0; p2 < 600 && rc < 300; p2++) {
            if (s_kept[p2]) out_keep[rc++] = (float)s_ord[p2];
        }
        for (; rc < 300; rc++) out_keep[rc] = -1.0f;
    }
}

// ---------------- launch ----------------
extern "C" void kernel_launch(void* const* d_in, const int* in_sizes, int n_in,
                              void* d_out, int out_size)
{
    const float* feat = (const float*)d_in[0];
    const float* Wps  = (const float*)d_in[1];
    const float* bps  = (const float*)d_in[2];
    const float* Wbb  = (const float*)d_in[3];
    const float* bbb  = (const float*)d_in[4];
    const float* rois = (const float*)d_in[5];

    float* out = (float*)d_out;
    float* o_cls  = out;
    float* o_res  = out + 1200;
    float* o_sc   = out + 1800;
    float* o_mask = out + 2400;
    float* o_ra   = out + 237600;
    float* o_bb   = out + 240600;
    float* o_keep = out + 243000;

    float *p_ps, *p_bb, *p_off, *p_ra, *p_sc;
    uint4 *p_A, *p_B;
    cudaGetSymbolAddress((void**)&p_ps, g_ps);
    cudaGetSymbolAddress((void**)&p_bb, g_bb);
    cudaGetSymbolAddress((void**)&p_off, g_off);
    cudaGetSymbolAddress((void**)&p_ra, g_roisall);
    cudaGetSymbolAddress((void**)&p_sc, g_scores);
    cudaGetSymbolAddress((void**)&p_A, g_Asp);
    cudaGetSymbolAddress((void**)&p_B, g_Bsp);

    cudaFuncSetAttribute(gemm_mma, cudaFuncAttributeMaxDynamicSharedMemorySize,
                         GEMM_SMEM);

    // 0. pre-split operands into fp16 hi/lo frag order
    prep_A<<<12800, 256>>>(feat, p_A);
    prep_B<<<392, 256>>>(Wps, Wbb, p_B);
    // 1. feature maps (fp16x3 mma)
    gemm_mma<<<dim3(200, 2), 256, GEMM_SMEM>>>(p_A, p_B, bps, bbb, p_ps, p_bb);
    // 2. offsets for the original 300 rois
    pooled4_kernel<<<300, 256>>>(rois, p_bb, p_off);
    // 3. proposals + rois_all
    proposal_kernel<<<2, 256>>>(rois, p_off, p_ra, o_ra);
    // 4. bbox for all 600 rois
    pooled4_kernel<<<600, 256>>>(p_ra, p_bb, o_bb);
    // 5. cls / score / mask for all 600 rois
    cls_mask_kernel<<<600, 256>>>(p_ra, p_ps, o_cls, o_res, o_sc, o_mask, p_sc);
    // 6. NMS
    nms_kernel<<<1, 640>>>(p_ra, p_sc, o_keep);
}

// round 6
// speedup vs baseline: 2.1089x; 1.0055x over previous
#include <cuda_runtime.h>
#include <cuda_fp16.h>
#include <math.h>
#include <stdint.h>
#include <float.h>

// ---------------- Scratch (device globals; no allocation allowed) ----------------
__device__ float g_ps[25600 * 196];     // ps_map
__device__ float g_bb[25600 * 196];     // bb_map
__device__ float g_off[300 * 4];
__device__ float g_roisall[600 * 5];
__device__ float g_scores[600];
// pre-split fp16 operands, mma-fragment ordered
__device__ uint4 g_Asp[6553600];        // 104.9 MB: [stage 6400][hi 512 | lo 512]
__device__ uint4 g_Bsp[100352];         // 1.6 MB

#define A_SCALE 64.0f
#define B_SCALE 1024.0f
#define INV_SCALE (1.0f / 65536.0f)

// ================= helpers =================
__device__ __forceinline__ uint32_t smem_u32(const void* p) {
    uint32_t a;
    asm("{ .reg .u64 t; cvta.to.shared.u64 t, %1; cvt.u32.u64 %0, t; }" : "=r"(a) : "l"(p));
    return a;
}
__device__ __forceinline__ void cpa16(uint32_t saddr, const void* gptr) {
    asm volatile("cp.async.cg.shared.global [%0], [%1], 16;" :: "r"(saddr), "l"(gptr));
}
#define CP_COMMIT() asm volatile("cp.async.commit_group;" ::: "memory")
#define CP_WAIT1()  asm volatile("cp.async.wait_group 1;" ::: "memory")
#define CP_WAIT0()  asm volatile("cp.async.wait_group 0;" ::: "memory")

__device__ __forceinline__ void splith(float x, __half& h, __half& l) {
    h = __float2half_rn(x);
    l = __float2half_rn(x - __half2float(h));
}
__device__ __forceinline__ uint32_t packh2(__half a, __half b) {
    __half2 v = __halves2half2(a, b);
    return *reinterpret_cast<uint32_t*>(&v);
}

__device__ __forceinline__ void mma_f16(float c[4], const uint32_t a[4],
                                        uint32_t b0, uint32_t b1) {
    asm volatile(
        "mma.sync.aligned.m16n8k16.row.col.f32.f16.f16.f32 "
        "{%0,%1,%2,%3}, {%4,%5,%6,%7}, {%8,%9}, {%0,%1,%2,%3};"
        : "+f"(c[0]), "+f"(c[1]), "+f"(c[2]), "+f"(c[3])
        : "r"(a[0]), "r"(a[1]), "r"(a[2]), "r"(a[3]), "r"(b0), "r"(b1));
}

// ================= prep_A: feat -> fp16 hi/lo, frag order ================
__global__ __launch_bounds__(256) void prep_A(const float* __restrict__ feat,
                                              uint4* __restrict__ Asp)
{
    long i = (long)blockIdx.x * 256 + threadIdx.x;   // 0 .. 3,276,799
    int lane = (int)(i & 31);
    int wid = (int)((i >> 5) & 7);
    int ks = (int)((i >> 8) & 1);
    long stage = i >> 9;                              // rt*32 + kt
    int kt = (int)(stage & 31);
    long rt = stage >> 5;
    int g = lane >> 2, t = lane & 3;
    long row = rt * 128 + wid * 16 + g;
    int k = kt * 32 + ks * 16 + 2 * t;

    const float* p = feat + row * 1024 + k;
    float2 u0 = *reinterpret_cast<const float2*>(p);
    float2 u1 = *reinterpret_cast<const float2*>(p + 8);
    float2 u2 = *reinterpret_cast<const float2*>(p + 8192);
    float2 u3 = *reinterpret_cast<const float2*>(p + 8200);

    __half h0a, l0a, h0b, l0b, h1a, l1a, h1b, l1b;
    __half h2a, l2a, h2b, l2b, h3a, l3a, h3b, l3b;
    splith(u0.x * A_SCALE, h0a, l0a); splith(u0.y * A_SCALE, h0b, l0b);
    splith(u1.x * A_SCALE, h1a, l1a); splith(u1.y * A_SCALE, h1b, l1b);
    splith(u2.x * A_SCALE, h2a, l2a); splith(u2.y * A_SCALE, h2b, l2b);
    splith(u3.x * A_SCALE, h3a, l3a); splith(u3.y * A_SCALE, h3b, l3b);

    uint4 hi = make_uint4(packh2(h0a, h0b), packh2(h2a, h2b),
                          packh2(h1a, h1b), packh2(h3a, h3b));
    uint4 lo = make_uint4(packh2(l0a, l0b), packh2(l2a, l2b),
                          packh2(l1a, l1b), packh2(l3a, l3b));
    int slot = (ks * 8 + wid) * 32 + lane;
    Asp[stage * 1024 + slot] = hi;
    Asp[stage * 1024 + 512 + slot] = lo;
}

// ================= prep_B ================
__global__ __launch_bounds__(256) void prep_B(const float* __restrict__ Wps,
                                              const float* __restrict__ Wbb,
                                              uint4* __restrict__ Bsp)
{
    int i = blockIdx.x * 256 + threadIdx.x;          // 0 .. 100,351
    if (i >= 100352) return;
    int ntc, nbase, base;
    if (i < 51200) { ntc = 25; nbase = 0; base = 0; }
    else           { ntc = 24; nbase = 200; base = 51200; }
    int li = i - base;
    int lane = li & 31;
    int j = li >> 5;
    int nt = j % ntc; j /= ntc;
    int ks = j & 1;
    int kt = j >> 1;
    int g = lane >> 2, t = lane & 3;
    int n = nbase + nt * 8 + g;
    int k = kt * 32 + ks * 16 + 2 * t;

    const float* W = (n < 196) ? Wps : Wbb;
    int nn = (n < 196) ? n : n - 196;
    float w0 = W[(size_t)k * 196 + nn] * B_SCALE;
    float w1 = W[(size_t)(k + 1) * 196 + nn] * B_SCALE;
    float w2 = W[(size_t)(k + 8) * 196 + nn] * B_SCALE;
    float w3 = W[(size_t)(k + 9) * 196 + nn] * B_SCALE;

    __half h0, l0, h1, l1, h2, l2, h3, l3;
    splith(w0, h0, l0); splith(w1, h1, l1);
    splith(w2, h2, l2); splith(w3, h3, l3);
    Bsp[i] = make_uint4(packh2(h0, h1), packh2(h2, h3),
                        packh2(l0, l1), packh2(l2, l3));
}

// ================= GEMM: fp16x3 mma, 3-stage pipeline ================
// grid 400 linear: mt = bx>>1 (A shared in L2 between the pair), nb = bx&1.
#define ABUF 16384
#define BBUF 25600
#define GEMM_SMEM (3 * (ABUF + BBUF))   // 125952

template<int NTC, int NBASE, int BOFF>
__device__ __forceinline__ void gemm_body(
    const uint4* __restrict__ Asp, const uint4* __restrict__ Bsp,
    const float* __restrict__ bps, const float* __restrict__ bbb,
    float* __restrict__ Cps, float* __restrict__ Cbb, char* smem, int mt)
{
    const int tid = threadIdx.x;
    const int lane = tid & 31;
    const int wid = tid >> 5;
    const int g = lane >> 2;
    const int t = lane & 3;
    const uint32_t sbase = smem_u32(smem);

    float c[NTC][4];
#pragma unroll
    for (int nt = 0; nt < NTC; nt++)
#pragma unroll
        for (int j = 0; j < 4; j++) c[nt][j] = 0.0f;

    auto copy_stage = [&](int s, int buf) {
        const uint4* ga = Asp + ((size_t)(mt * 32 + s)) * 1024;
        uint32_t sa = sbase + buf * ABUF;
#pragma unroll
        for (int i = 0; i < 4; i++) {
            int o = tid + i * 256;
            cpa16(sa + o * 16, ga + o);
        }
        const uint4* gb = Bsp + BOFF + (size_t)s * (NTC * 64);
        uint32_t sB = sbase + 3 * ABUF + buf * BBUF;
#pragma unroll
        for (int i = 0; i < 6; i++) {
            int o = tid + i * 256;
            cpa16(sB + o * 16, gb + o);
        }
        if (NTC == 25 && tid < 64) {
            int o = tid + 1536;
            cpa16(sB + o * 16, gb + o);
        }
        CP_COMMIT();
    };

    copy_stage(0, 0);
    copy_stage(1, 1);

    for (int s = 0; s < 32; ++s) {
        if (s < 31) CP_WAIT1(); else CP_WAIT0();
        __syncthreads();
        // prefetch s+2 into the buffer consumed at s-1 (all warps are past it)
        if (s + 2 < 32) copy_stage(s + 2, (s + 2) % 3);

        const int buf = s % 3;
        const uint4* Ah = reinterpret_cast<const uint4*>(smem + buf * ABUF);
        const uint4* Bs = reinterpret_cast<const uint4*>(smem + 3 * ABUF + buf * BBUF);

#pragma unroll
        for (int ks = 0; ks < 2; ks++) {
            int slot = (ks * 8 + wid) * 32 + lane;
            uint4 hv = Ah[slot];
            uint4 lv = Ah[512 + slot];
            uint32_t ah[4] = {hv.x, hv.y, hv.z, hv.w};
            uint32_t al[4] = {lv.x, lv.y, lv.z, lv.w};
#pragma unroll
            for (int nt = 0; nt < NTC; nt++) {
                uint4 q = Bs[(ks * NTC + nt) * 32 + lane];
                mma_f16(c[nt], al, q.x, q.y);   // lo_a * hi_b
                mma_f16(c[nt], ah, q.z, q.w);   // hi_a * lo_b
                mma_f16(c[nt], ah, q.x, q.y);   // hi_a * hi_b
            }
        }
    }

    // epilogue: unscale + bias + float2 stores
    const int r0 = mt * 128 + wid * 16 + g;
#pragma unroll
    for (int nt = 0; nt < NTC; nt++) {
        int gc = NBASE + nt * 8 + t * 2;
        float bias0, bias1;
        float* Cout;
        int cc;
        if (gc < 196) { bias0 = bps[gc]; bias1 = bps[gc + 1]; Cout = Cps; cc = gc; }
        else { bias0 = bbb[gc - 196]; bias1 = bbb[gc - 195]; Cout = Cbb; cc = gc - 196; }
        float2 w0 = make_float2(c[nt][0] * INV_SCALE + bias0,
                                c[nt][1] * INV_SCALE + bias1);
        float2 w1 = make_float2(c[nt][2] * INV_SCALE + bias0,
                                c[nt][3] * INV_SCALE + bias1);
        *reinterpret_cast<float2*>(&Cout[(size_t)r0 * 196 + cc]) = w0;
        *reinterpret_cast<float2*>(&Cout[(size_t)(r0 + 8) * 196 + cc]) = w1;
    }
}

__global__ __launch_bounds__(256, 1) void gemm_mma(
    const uint4* __restrict__ Asp, const uint4* __restrict__ Bsp,
    const float* __restrict__ bps, const float* __restrict__ bbb,
    float* __restrict__ Cps, float* __restrict__ Cbb)
{
    extern __shared__ char smem[];
    int mt = blockIdx.x >> 1;
    if ((blockIdx.x & 1) == 0)
        gemm_body<25, 0, 0>(Asp, Bsp, bps, bbb, Cps, Cbb, smem, mt);
    else
        gemm_body<24, 200, 51200>(Asp, Bsp, bps, bbb, Cps, Cbb, smem, mt);
}

// ---------------- Bilinear PS-ROI sample ----------------
__device__ __forceinline__ void ps_sample4(const float* __restrict__ map,
                                           float y, float x, int cbase, float v[4])
{
    float y0f = floorf(y), x0f = floorf(x);
    float wy = y - y0f, wx = x - x0f;
    int y0 = (int)y0f; y0 = min(max(y0, 0), 159);
    int y1c = min(y0 + 1, 159);
    int x0 = (int)x0f; x0 = min(max(x0, 0), 159);
    int x1c = min(x0 + 1, 159);

    const float* p00 = map + (size_t)(y0 * 160 + x0) * 196 + cbase;
    const float* p01 = map + (size_t)(y0 * 160 + x1c) * 196 + cbase;
    const float* p10 = map + (size_t)(y1c * 160 + x0) * 196 + cbase;
    const float* p11 = map + (size_t)(y1c * 160 + x1c) * 196 + cbase;

    float w00 = (1.0f - wy) * (1.0f - wx);
    float w01 = (1.0f - wy) * wx;
    float w10 = wy * (1.0f - wx);
    float w11 = wy * wx;
#pragma unroll
    for (int p = 0; p < 4; p++) {
        v[p] = p00[p * 49] * w00 + p01[p * 49] * w01 +
               p10[p * 49] * w10 + p11[p * 49] * w11;
    }
}

// ---------------- part2_2: pooled 4-vector per roi ----------------
__global__ __launch_bounds__(256) void pooled4_kernel(
    const float* __restrict__ rois,
    const float* __restrict__ map,
    float* __restrict__ out)
{
    int r = blockIdx.x;
    const float* roi = rois + (size_t)r * 5;
    float x1 = roi[1] * 0.125f;
    float yy1 = roi[2] * 0.125f;
    float x2 = roi[3] * 0.125f;
    float y2 = roi[4] * 0.125f;
    float bw = __fdiv_rn(x2 - x1, 7.0f);
    float bh = __fdiv_rn(y2 - yy1, 7.0f);

    int t = threadIdx.x;
    float v[4] = {0.f, 0.f, 0.f, 0.f};
    if (t < 196) {
        int yI = t / 14, xI = t % 14;
        int i = yI >> 1, sy = yI & 1;
        int j = xI >> 1, sx = xI & 1;
        float y = __fmaf_rn((float)i + (sy ? 0.75f : 0.25f), bh, yy1);
        float x = __fmaf_rn((float)j + (sx ? 0.75f : 0.25f), bw, x1);
        ps_sample4(map, y, x, i * 7 + j, v);
    }

    __shared__ float red[4][256];
#pragma unroll
    for (int p = 0; p < 4; p++) red[p][t] = v[p];
    __syncthreads();
    for (int s = 128; s > 0; s >>= 1) {
        if (t < s) {
#pragma unroll
            for (int p = 0; p < 4; p++) red[p][t] += red[p][t + s];
        }
        __syncthreads();
    }
    if (t < 4) out[(size_t)r * 4 + t] = __fdiv_rn(red[t][0], 196.0f);
}

// ---------------- proposals ----------------
__global__ void proposal_kernel(const float* __restrict__ rois,
                                const float* __restrict__ off,
                                float* __restrict__ roisall,
                                float* __restrict__ out_roisall)
{
    int r = blockIdx.x * blockDim.x + threadIdx.x;
    if (r >= 300) return;

#pragma unroll
    for (int c = 0; c < 5; c++) {
        float val = rois[(size_t)r * 5 + c];
        roisall[(size_t)r * 5 + c] = val;
        out_roisall[(size_t)r * 5 + c] = val;
    }

    float x1 = rois[r * 5 + 1], y1 = rois[r * 5 + 2];
    float x2 = rois[r * 5 + 3], y2 = rois[r * 5 + 4];
    float w = x2 - x1 + 1.0f, h = y2 - y1 + 1.0f;
    float cx = x1 + 0.5f * w, cy = y1 + 0.5f * h;
    float dx = off[r * 4 + 0], dy = off[r * 4 + 1];
    float dw = off[r * 4 + 2], dh = off[r * 4 + 3];
    float pcx = dx * w + cx, pcy = dy * h + cy;
    float edw = (float)exp((double)dw);
    float edh = (float)exp((double)dh);
    float pw = edw * w, ph = edh * h;
    float px1 = pcx - 0.5f * pw, py1 = pcy - 0.5f * ph;
    float px2 = pcx + 0.5f * pw, py2 = pcy + 0.5f * ph;
    px1 = fminf(fmaxf(px1, 0.0f), 1279.0f);
    py1 = fminf(fmaxf(py1, 0.0f), 1279.0f);
    px2 = fminf(fmaxf(px2, 0.0f), 1279.0f);
    py2 = fminf(fmaxf(py2, 0.0f), 1279.0f);

    int rr = 300 + r;
    float vals[5] = {0.0f, px1, py1, px2, py2};
#pragma unroll
    for (int c = 0; c < 5; c++) {
        roisall[(size_t)rr * 5 + c] = vals[c];
        out_roisall[(size_t)rr * 5 + c] = vals[c];
    }
}

// ---------------- part2_1 ----------------
__global__ __launch_bounds__(256) void cls_mask_kernel(
    const float* __restrict__ roisall,
    const float* __restrict__ psmap,
    float* __restrict__ out_cls,
    float* __restrict__ out_res,
    float* __restrict__ out_score,
    float* __restrict__ out_mask,
    float* __restrict__ scores)
{
    int r = blockIdx.x;
    const float* roi = roisall + (size_t)r * 5;
    float x1 = roi[1] * 0.125f;
    float yy1 = roi[2] * 0.125f;
    float x2 = roi[3] * 0.125f;
    float y2 = roi[4] * 0.125f;
    float bw = __fdiv_rn(x2 - x1, 7.0f);
    float bh = __fdiv_rn(y2 - yy1, 7.0f);

    int t = threadIdx.x;
    float v[4] = {0.f, 0.f, 0.f, 0.f};
    float cm0 = 0.f, cm1 = 0.f;
    if (t < 196) {
        int yI = t / 14, xI = t % 14;
        int i = yI >> 1, sy = yI & 1;
        int j = xI >> 1, sx = xI & 1;
        float y = __fmaf_rn((float)i + (sy ? 0.75f : 0.25f), bh, yy1);
        float x = __fmaf_rn((float)j + (sx ? 0.75f : 0.25f), bw, x1);
        ps_sample4(psmap, y, x, i * 7 + j, v);
        cm0 = fmaxf(v[0], v[2]);
        cm1 = fmaxf(v[1], v[3]);
    }

    __shared__ float red[2][256];
    __shared__ int s_res;
    red[0][t] = cm0;
    red[1][t] = cm1;
    __syncthreads();
    for (int s = 128; s > 0; s >>= 1) {
        if (t < s) {
            red[0][t] += red[0][t + s];
            red[1][t] += red[1][t + s];
        }
        __syncthreads();
    }
    if (t == 0) {
        float a0 = __fdiv_rn(red[0][0], 196.0f);
        float a1 = __fdiv_rn(red[1][0], 196.0f);
        double m = (a0 > a1) ? (double)a0 : (double)a1;
        double e0 = exp((double)a0 - m);
        double e1 = exp((double)a1 - m);
        double inv = 1.0 / (e0 + e1);
        float c0 = (float)(e0 * inv);
        float c1 = (float)(e1 * inv);
        int res = (c1 > c0) ? 1 : 0;
        float sc = fmaxf(c0, c1);
        out_cls[(size_t)r * 2 + 0] = c0;
        out_cls[(size_t)r * 2 + 1] = c1;
        out_res[r] = (float)res;
        out_score[r] = sc;
        scores[r] = sc;
        s_res = res;
    }
    __syncthreads();

    if (t < 196) {
        int copy = s_res;
        float m0 = v[copy], m1 = v[2 + copy];
        float mm = fmaxf(m0, m1);
        float e0 = expf(m0 - mm);
        float e1 = expf(m1 - mm);
        float s = e0 + e1;
        out_mask[(size_t)r * 392 + t * 2 + 0] = __fdiv_rn(e0, s);
        out_mask[(size_t)r * 392 + t * 2 + 1] = __fdiv_rn(e1, s);
    }
}

// ---------------- NMS ----------------
__global__ __launch_bounds__(640) void nms_kernel(
    const float* __restrict__ roisall,
    const float* __restrict__ scores,
    float* __restrict__ out_keep)
{
    __shared__ float s_sc[600];
    __shared__ int s_ord[600];
    __shared__ float bxs[600 * 4];
    __shared__ float s_area[600];
    __shared__ unsigned char s_kept[600];

    int t = threadIdx.x;
    if (t < 600) s_sc[t] = scores[t];
    __syncthreads();

    if (t < 600) {
        float si = s_sc[t];
        int cnt = 0;
        for (int j = 0; j < 600; j++) {
            float sj = s_sc[j];
            cnt += (sj > si) || (sj == si && j < t);
        }
        s_ord[cnt] = t;
    }
    __syncthreads();

    float bx1 = 0.f, by1 = 0.f, bx2 = 0.f, by2 = 0.f, myArea = 0.f;
    bool kept_self = false;
    if (t < 600) {
        int o = s_ord[t];
        bx1 = roisall[(size_t)o * 5 + 1];
        by1 = roisall[(size_t)o * 5 + 2];
        bx2 = roisall[(size_t)o * 5 + 3];
        by2 = roisall[(size_t)o * 5 + 4];
        myArea = fmaxf(bx2 - bx1, 0.0f) * fmaxf(by2 - by1, 0.0f);
        bxs[t * 4 + 0] = bx1;
        bxs[t * 4 + 1] = by1;
        bxs[t * 4 + 2] = bx2;
        bxs[t * 4 + 3] = by2;
        s_area[t] = myArea;
    }
    __syncthreads();

    for (int i = 0; i < 600; i++) {
        bool p = false;
        if (t < i && kept_self) {
            float cx1 = bxs[i * 4 + 0], cy1 = bxs[i * 4 + 1];
            float cx2 = bxs[i * 4 + 2], cy2 = bxs[i * 4 + 3];
            float ix1 = fmaxf(cx1, bx1), iy1 = fmaxf(cy1, by1);
            float ix2 = fminf(cx2, bx2), iy2 = fminf(cy2, by2);
            float inter = fmaxf(ix2 - ix1, 0.0f) * fmaxf(iy2 - iy1, 0.0f);
            float denom = s_area[i] + myArea - inter + 1e-8f;
            float iou = __fdiv_rn(inter, denom);
            p = iou > 0.3f;
        }
        int any = __syncthreads_or((int)p);
        if (t == i) kept_self = !any;
    }

    if (t < 600) s_kept[t] = kept_self ? 1 : 0;
    __syncthreads();

    if (t == 0) {
        int rc = 0;
        for (int p2 = 0; p2 < 600 && rc < 300; p2++) {
            if (s_kept[p2]) out_keep[rc++] = (float)s_ord[p2];
        }
        for (; rc < 300; rc++) out_keep[rc] = -1.0f;
    }
}

// ---------------- launch ----------------
extern "C" void kernel_launch(void* const* d_in, const int* in_sizes, int n_in,
                              void* d_out, int out_size)
{
    const float* feat = (const float*)d_in[0];
    const float* Wps  = (const float*)d_in[1];
    const float* bps  = (const float*)d_in[2];
    const float* Wbb  = (const float*)d_in[3];
    const float* bbb  = (const float*)d_in[4];
    const float* rois = (const float*)d_in[5];

    float* out = (float*)d_out;
    float* o_cls  = out;
    float* o_res  = out + 1200;
    float* o_sc   = out + 1800;
    float* o_mask = out + 2400;
    float* o_ra   = out + 237600;
    float* o_bb   = out + 240600;
    float* o_keep = out + 243000;

    float *p_ps, *p_bb, *p_off, *p_ra, *p_sc;
    uint4 *p_A, *p_B;
    cudaGetSymbolAddress((void**)&p_ps, g_ps);
    cudaGetSymbolAddress((void**)&p_bb, g_bb);
    cudaGetSymbolAddress((void**)&p_off, g_off);
    cudaGetSymbolAddress((void**)&p_ra, g_roisall);
    cudaGetSymbolAddress((void**)&p_sc, g_scores);
    cudaGetSymbolAddress((void**)&p_A, g_Asp);
    cudaGetSymbolAddress((void**)&p_B, g_Bsp);

    cudaFuncSetAttribute(gemm_mma, cudaFuncAttributeMaxDynamicSharedMemorySize,
                         GEMM_SMEM);

    // 0. pre-split operands into fp16 hi/lo frag order
    prep_A<<<12800, 256>>>(feat, p_A);
    prep_B<<<392, 256>>>(Wps, Wbb, p_B);
    // 1. feature maps (fp16x3 mma, paired N-blocks for L2 A reuse)
    gemm_mma<<<400, 256, GEMM_SMEM>>>(p_A, p_B, bps, bbb, p_ps, p_bb);
    // 2. offsets for the original 300 rois
    pooled4_kernel<<<300, 256>>>(rois, p_bb, p_off);
    // 3. proposals + rois_all
    proposal_kernel<<<2, 256>>>(rois, p_off, p_ra, o_ra);
    // 4. bbox for all 600 rois
    pooled4_kernel<<<600, 256>>>(p_ra, p_bb, o_bb);
    // 5. cls / score / mask for all 600 rois
    cls_mask_kernel<<<600, 256>>>(p_ra, p_ps, o_cls, o_res, o_sc, o_mask, p_sc);
    // 6. NMS
    nms_kernel<<<1, 640>>>(p_ra, p_sc, o_keep);
}